// round 14
// baseline (speedup 1.0000x reference)
#include <cuda_runtime.h>
#include <cuda_bf16.h>
#include <cstddef>
#include <cstdint>

#define Bn 8
#define Cc 256
#define Nn 4096      // 64*64 spatial
#define Mm 1024      // 32*32 pooled
#define Dd 32
#define Dv 128

// Scratch (device globals; no allocations allowed)
// g_theta: (n, i, d) fp32 plain
// g_phib:  (n, j, d) bf16, d reordered per row for uint4 fragment gather
// g_gp:    (n, v, j) bf16, j reordered per 32-j slice for uint4 gather
__device__ float          g_theta[Bn * Nn * Dd];
__device__ __nv_bfloat16  g_phib [Bn * Mm * Dd];
__device__ __nv_bfloat16  g_gp   [Bn * Dv * Mm];

__device__ __forceinline__ void mma_tf32(float c[4], const uint32_t a[4],
                                         uint32_t b0, uint32_t b1) {
    asm volatile("mma.sync.aligned.m16n8k8.row.col.f32.tf32.tf32.f32 "
        "{%0,%1,%2,%3}, {%4,%5,%6,%7}, {%8,%9}, {%0,%1,%2,%3};"
        : "+f"(c[0]), "+f"(c[1]), "+f"(c[2]), "+f"(c[3])
        : "r"(a[0]), "r"(a[1]), "r"(a[2]), "r"(a[3]), "r"(b0), "r"(b1));
}
__device__ __forceinline__ void mma_bf16(float c[4], const uint32_t a[4],
                                         uint32_t b0, uint32_t b1) {
    asm volatile("mma.sync.aligned.m16n8k16.row.col.f32.bf16.bf16.f32 "
        "{%0,%1,%2,%3}, {%4,%5,%6,%7}, {%8,%9}, {%0,%1,%2,%3};"
        : "+f"(c[0]), "+f"(c[1]), "+f"(c[2]), "+f"(c[3])
        : "r"(a[0]), "r"(a[1]), "r"(a[2]), "r"(a[3]), "r"(b0), "r"(b1));
}
__device__ __forceinline__ uint32_t pkbf(float lo, float hi) {
    uint32_t r;
    asm("cvt.rn.bf16x2.f32 %0, %1, %2;" : "=r"(r) : "f"(hi), "f"(lo));
    return r;
}
__device__ __forceinline__ void cp16(void* dst_smem, const void* src) {
    uint32_t d = (uint32_t)__cvta_generic_to_shared(dst_smem);
    asm volatile("cp.async.cg.shared.global [%0], [%1], 16;\n" :: "r"(d), "l"(src));
}
__device__ __forceinline__ void cp_commit() {
    asm volatile("cp.async.commit_group;\n");
}
template<int N> __device__ __forceinline__ void cp_wait() {
    asm volatile("cp.async.wait_group %0;\n" :: "n"(N));
}
// position of element r within its 8-group under [0,4,1,5,2,6,3,7] order
__device__ __forceinline__ int perm8(int r) {
    return (r < 4) ? 2 * r : 2 * (r - 4) + 1;
}

// ---------------------------------------------------------------------------
// Kernel 1: fused projections + maxpool, tf32 MMA, single-barrier pipeline.
// phi/g written bf16 with uint4-fragment reordering (see kernel 2 layout).
// ---------------------------------------------------------------------------
#define WS  36
#define XSS 136
#define YSS 132

__global__ void __launch_bounds__(256, 3) proj_mma_kernel(
    const float* __restrict__ x,
    const float* __restrict__ theta_w, const float* __restrict__ theta_b,
    const float* __restrict__ phi_w,   const float* __restrict__ phi_b,
    const float* __restrict__ g_w,     const float* __restrict__ g_b)
{
    extern __shared__ float sm[];
    float* Ws = sm;                    // 2 x 64 x 36
    float* Xs = sm + 2 * 64 * WS;      // 2 x 32 x 136
    float* Ys = sm;                    // 64 x 132 (aliases pipeline)

    const int bi  = blockIdx.x;
    const int grp = blockIdx.y;
    const int n   = blockIdx.z;
    const int t   = threadIdx.x;
    const int w   = t >> 5, lane = t & 31;
    const int gq  = lane >> 2, tq = lane & 3;
    const int mrow = (w & 3) * 16;
    const int nc0  = (w >> 2) * 64;
    const int base = bi * 128;

    const float* xb = x + (size_t)n * Cc * Nn;

    auto issue = [&](int c8) {
        int kc = c8 * 32;
        float* Wb = Ws + (c8 & 1) * 64 * WS;
        float* Xb = Xs + (c8 & 1) * 32 * XSS;
#pragma unroll
        for (int it = 0; it < 2; it++) {
            int idx = t + it * 256;
            int r = idx >> 3, kq = (idx & 7) * 4;
            const float* src;
            if (grp == 0) src = (r < 32) ? &theta_w[r * Cc + kc + kq]
                                         : &phi_w[(r - 32) * Cc + kc + kq];
            else          src = &g_w[((grp - 1) * 64 + r) * Cc + kc + kq];
            cp16(&Wb[r * WS + kq], src);
        }
#pragma unroll
        for (int it = 0; it < 4; it++) {
            int idx = t + it * 256;
            int k = idx >> 5, i4 = (idx & 31) * 4;
            cp16(&Xb[k * XSS + i4], &xb[(size_t)(kc + k) * Nn + base + i4]);
        }
        cp_commit();
    };

    float acc[8][4];
#pragma unroll
    for (int nt = 0; nt < 8; nt++)
#pragma unroll
        for (int c = 0; c < 4; c++) acc[nt][c] = 0.f;

    issue(0);
    for (int c8 = 0; c8 < 8; c8++) {
        cp_wait<0>();
        __syncthreads();
        if (c8 + 1 < 8) issue(c8 + 1);

        const float* Wb = Ws + (c8 & 1) * 64 * WS;
        const float* Xb = Xs + (c8 & 1) * 32 * XSS;
#pragma unroll
        for (int ks = 0; ks < 4; ks++) {
            uint32_t a[4];
            a[0] = __float_as_uint(Wb[(mrow + gq    ) * WS + ks * 8 + tq    ]);
            a[1] = __float_as_uint(Wb[(mrow + gq + 8) * WS + ks * 8 + tq    ]);
            a[2] = __float_as_uint(Wb[(mrow + gq    ) * WS + ks * 8 + tq + 4]);
            a[3] = __float_as_uint(Wb[(mrow + gq + 8) * WS + ks * 8 + tq + 4]);
#pragma unroll
            for (int nt = 0; nt < 8; nt++) {
                uint32_t b0 = __float_as_uint(Xb[(ks * 8 + tq    ) * XSS + nc0 + nt * 8 + gq]);
                uint32_t b1 = __float_as_uint(Xb[(ks * 8 + tq + 4) * XSS + nc0 + nt * 8 + gq]);
                mma_tf32(acc[nt], a, b0, b1);
            }
        }
    }
    __syncthreads();   // all fragment reads done before Ys aliases pipeline

    {
        int r0 = mrow + gq, r1 = mrow + gq + 8;
        float b0, b1;
        if (grp == 0) {
            b0 = (r0 < 32) ? theta_b[r0] : phi_b[r0 - 32];
            b1 = (r1 < 32) ? theta_b[r1] : phi_b[r1 - 32];
        } else {
            b0 = g_b[(grp - 1) * 64 + r0];
            b1 = g_b[(grp - 1) * 64 + r1];
        }
#pragma unroll
        for (int nt = 0; nt < 8; nt++) {
            int col = nc0 + nt * 8 + tq * 2;
            *(float2*)&Ys[r0 * YSS + col] = make_float2(acc[nt][0] + b0, acc[nt][1] + b0);
            *(float2*)&Ys[r1 * YSS + col] = make_float2(acc[nt][2] + b1, acc[nt][3] + b1);
        }
    }
    __syncthreads();

    if (grp == 0) {
        // theta rows 0..31 -> (n, i, d) fp32
        for (int idx = t; idx < 32 * 128; idx += 256) {
            int o = idx & 31, i = idx >> 5;
            g_theta[((size_t)n * Nn + base + i) * Dd + o] = Ys[o * YSS + i];
        }
        // phi rows 32..63 -> maxpool -> (n, j, d_reordered) bf16
        // row layout (16 words): pos = tq*4 + kc*2 + sub  (sub: word tq vs tq+4)
        for (int idx = t; idx < 32 * 32; idx += 256) {
            int o = idx & 31, jw = idx >> 5;
            const float* yr = &Ys[(32 + o) * YSS];
            float m0 = fmaxf(yr[2 * jw],      yr[2 * jw + 1]);
            float m1 = fmaxf(yr[64 + 2 * jw], yr[64 + 2 * jw + 1]);
            int kc = o >> 4, wloc = (o & 15) >> 1, lo = o & 1;
            int pos = (((wloc & 3) * 4) + kc * 2 + (wloc >> 2)) * 2 + lo;
            g_phib[((size_t)n * Mm + bi * 32 + jw) * Dd + pos] =
                __float2bfloat16(fmaxf(m0, m1));
        }
    } else {
        int vbase = (grp - 1) * 64;
        // g -> maxpool -> (n, v, j_reordered) bf16
        // 32-j slice (16 words): pos = tq*4 + grp16*2 + sub
        for (int idx = t; idx < 64 * 32; idx += 256) {
            int jw = idx & 31, v = idx >> 5;
            const float* yr = &Ys[v * YSS];
            float m0 = fmaxf(yr[2 * jw],      yr[2 * jw + 1]);
            float m1 = fmaxf(yr[64 + 2 * jw], yr[64 + 2 * jw + 1]);
            int wl = jw >> 1, lo = jw & 1;
            int grp16 = wl >> 3, wloc = wl & 7;
            int pos = (((wloc & 3) * 4) + grp16 * 2 + (wloc >> 2)) * 2 + lo;
            g_gp[((size_t)n * Dv + vbase + v) * Mm + bi * 32 + pos] =
                __float2bfloat16(fmaxf(m0, m1));
        }
    }
}

// ---------------------------------------------------------------------------
// Kernel 2: FUSED flash attention + out conv + residual. ALL-bf16 MMA,
// all main-loop B-fragment gathers via single LDS.128 (uint4).
// phi smem: row stride 16 words (no pad, phase-disjoint banks).
// g smem:   row stride 80 words (64 data + 16 pad, ≡16 mod 32).
// grid (32 q-tiles, 8 batches), 256 threads = 8 warps x 16 q.
// ---------------------------------------------------------------------------
#define KB    128
#define PHW   16   // phi row stride in words
#define GSW   80   // g row stride in words
#define WSTR  72   // W pane row stride in words (phase 3)
#define NSTG  2

__global__ void __launch_bounds__(256, 2) attn_fused_kernel(
    const float* __restrict__ x,
    const float* __restrict__ out_w,
    const float* __restrict__ out_b,
    const float* __restrict__ gamma,
    float* __restrict__ out)
{
    extern __shared__ float sm[];
    uint32_t* Phw = (uint32_t*)sm;                         // 2 x 128 x 16 words
    uint32_t* Gsw = (uint32_t*)sm + NSTG * KB * PHW;       // 2 x 128 x 80 words
    uint32_t* Wsw = (uint32_t*)sm;                         // phase3: 256 x 72 words

    const int n  = blockIdx.y;
    const int i0 = blockIdx.x * 128;
    const int t  = threadIdx.x;
    const int w  = t >> 5;
    const int lane = t & 31;
    const int qb = w * 16;
    const int gq = lane >> 2;
    const int tq = lane & 3;

    // Q A-fragments, bf16 k16 x 2 chunks (persist)
    uint32_t qa[2][4];
    {
        const float* th = g_theta + ((size_t)n * Nn + i0 + qb) * Dd;
#pragma unroll
        for (int kc = 0; kc < 2; kc++) {
            qa[kc][0] = pkbf(th[(gq    ) * Dd + kc * 16 + 2 * tq],
                             th[(gq    ) * Dd + kc * 16 + 2 * tq + 1]);
            qa[kc][1] = pkbf(th[(gq + 8) * Dd + kc * 16 + 2 * tq],
                             th[(gq + 8) * Dd + kc * 16 + 2 * tq + 1]);
            qa[kc][2] = pkbf(th[(gq    ) * Dd + kc * 16 + 8 + 2 * tq],
                             th[(gq    ) * Dd + kc * 16 + 8 + 2 * tq + 1]);
            qa[kc][3] = pkbf(th[(gq + 8) * Dd + kc * 16 + 8 + 2 * tq],
                             th[(gq + 8) * Dd + kc * 16 + 8 + 2 * tq + 1]);
        }
    }

    auto issue = [&](int chunk) {
        int buf = chunk & 1;
        int jb = chunk * KB;
        uint32_t* Pb = Phw + buf * KB * PHW;
        uint32_t* Gb = Gsw + buf * Dv * GSW;
#pragma unroll
        for (int it = 0; it < 2; it++) {
            int idx = t + it * 256;                 // phi: 128 j x 4 cp16 -> 512
            int j = idx >> 2, c = idx & 3;
            cp16((__nv_bfloat16*)&Pb[j * PHW] + c * 8,
                 &g_phib[((size_t)n * Mm + jb + j) * Dd + c * 8]);
        }
#pragma unroll
        for (int it = 0; it < 8; it++) {
            int idx = t + it * 256;                 // g: 128 v x 16 cp16 -> 2048
            int vv = idx >> 4, p8 = (idx & 15) * 8;
            cp16((__nv_bfloat16*)&Gb[vv * GSW] + p8,
                 &g_gp[((size_t)n * Dv + vv) * Mm + jb + p8]);
        }
        cp_commit();
    };

    float oacc[16][4];
#pragma unroll
    for (int vt = 0; vt < 16; vt++)
#pragma unroll
        for (int c = 0; c < 4; c++) oacc[vt][c] = 0.f;

    float s0 = 0.f, s1 = 0.f;

    issue(0);
    for (int kb = 0; kb < Mm / KB; kb++) {
        cp_wait<0>();
        __syncthreads();
        if (kb + 1 < Mm / KB) issue(kb + 1);

        const uint32_t* Pw = Phw + (kb & 1) * KB * PHW;
        const uint32_t* Gb = Gsw + (kb & 1) * Dv * GSW;

        // per p-pair P (32 keys): energy 8 MMA from 4 LDS.128,
        // exp+pack, PV 32 MMA from 16 LDS.128.
#pragma unroll
        for (int P = 0; P < 4; P++) {
            float ea[4] = {0.f, 0.f, 0.f, 0.f};
            float eb[4] = {0.f, 0.f, 0.f, 0.f};
            float ec[4] = {0.f, 0.f, 0.f, 0.f};
            float ed[4] = {0.f, 0.f, 0.f, 0.f};
            {
                uint4 r0 = *(const uint4*)&Pw[((4*P    ) * 8 + gq) * PHW + tq * 4];
                uint4 r1 = *(const uint4*)&Pw[((4*P + 1) * 8 + gq) * PHW + tq * 4];
                uint4 r2 = *(const uint4*)&Pw[((4*P + 2) * 8 + gq) * PHW + tq * 4];
                uint4 r3 = *(const uint4*)&Pw[((4*P + 3) * 8 + gq) * PHW + tq * 4];
                mma_bf16(ea, qa[0], r0.x, r0.y);
                mma_bf16(eb, qa[0], r1.x, r1.y);
                mma_bf16(ec, qa[0], r2.x, r2.y);
                mma_bf16(ed, qa[0], r3.x, r3.y);
                mma_bf16(ea, qa[1], r0.z, r0.w);
                mma_bf16(eb, qa[1], r1.z, r1.w);
                mma_bf16(ec, qa[1], r2.z, r2.w);
                mma_bf16(ed, qa[1], r3.z, r3.w);
            }
            ea[0] = __expf(ea[0]); ea[1] = __expf(ea[1]);
            ea[2] = __expf(ea[2]); ea[3] = __expf(ea[3]);
            eb[0] = __expf(eb[0]); eb[1] = __expf(eb[1]);
            eb[2] = __expf(eb[2]); eb[3] = __expf(eb[3]);
            ec[0] = __expf(ec[0]); ec[1] = __expf(ec[1]);
            ec[2] = __expf(ec[2]); ec[3] = __expf(ec[3]);
            ed[0] = __expf(ed[0]); ed[1] = __expf(ed[1]);
            ed[2] = __expf(ed[2]); ed[3] = __expf(ed[3]);
            s0 += ea[0] + ea[1] + eb[0] + eb[1] + ec[0] + ec[1] + ed[0] + ed[1];
            s1 += ea[2] + ea[3] + eb[2] + eb[3] + ec[2] + ec[3] + ed[2] + ed[3];
            uint32_t pe[4], po[4];
            pe[0] = pkbf(ea[0], ea[1]);
            pe[1] = pkbf(ea[2], ea[3]);
            pe[2] = pkbf(eb[0], eb[1]);
            pe[3] = pkbf(eb[2], eb[3]);
            po[0] = pkbf(ec[0], ec[1]);
            po[1] = pkbf(ec[2], ec[3]);
            po[2] = pkbf(ed[0], ed[1]);
            po[3] = pkbf(ed[2], ed[3]);
#pragma unroll
            for (int vt = 0; vt < 16; vt++) {
                uint4 g4 = *(const uint4*)&Gb[(vt * 8 + gq) * GSW + P * 16 + tq * 4];
                mma_bf16(oacc[vt], pe, g4.x, g4.y);
                mma_bf16(oacc[vt], po, g4.z, g4.w);
            }
        }
    }

    // ---- exp-sum reduce (once) and O pack ----
    s0 += __shfl_xor_sync(0xffffffff, s0, 1);
    s0 += __shfl_xor_sync(0xffffffff, s0, 2);
    s1 += __shfl_xor_sync(0xffffffff, s1, 1);
    s1 += __shfl_xor_sync(0xffffffff, s1, 2);

    uint32_t oa[8][4];
    {
        const float inv0 = 1.f / s0;
        const float inv1 = 1.f / s1;
#pragma unroll
        for (int kc = 0; kc < 8; kc++) {
            oa[kc][0] = pkbf(oacc[2*kc  ][0] * inv0, oacc[2*kc  ][1] * inv0);
            oa[kc][1] = pkbf(oacc[2*kc  ][2] * inv1, oacc[2*kc  ][3] * inv1);
            oa[kc][2] = pkbf(oacc[2*kc+1][0] * inv0, oacc[2*kc+1][1] * inv0);
            oa[kc][3] = pkbf(oacc[2*kc+1][2] * inv1, oacc[2*kc+1][3] * inv1);
        }
    }
    __syncthreads();   // all warps done with pipeline smem before W pane aliasing

    // ---- phase 3: out conv (bf16). Full W pane [256 c x 64 words] loaded once.
    const float gm = gamma[0];

#pragma unroll
    for (int it = 0; it < 32; it++) {
        int idx = t + it * 256;                  // 8192: 256 c x 32 float4
        int r = idx >> 5, v4 = (idx & 31) * 4;
        float4 wv = *(const float4*)&out_w[(size_t)r * Dv + v4];
        uint32_t w0 = pkbf(wv.x, wv.y);
        uint32_t w1 = pkbf(wv.z, wv.w);
        int wi0 = v4 >> 1, wi1 = wi0 + 1;
        Wsw[r * WSTR + (wi0 & ~7) + perm8(wi0 & 7)] = w0;
        Wsw[r * WSTR + (wi1 & ~7) + perm8(wi1 & 7)] = w1;
    }
    __syncthreads();

#pragma unroll
    for (int pass = 0; pass < 4; pass++) {
        const int cbase = pass * 64;
#pragma unroll
        for (int nt = 0; nt < 8; nt++) {
            float acc[4] = {0.f, 0.f, 0.f, 0.f};
#pragma unroll
            for (int kc = 0; kc < 8; kc++) {
                uint2 bb = *(const uint2*)&Wsw[(cbase + nt * 8 + gq) * WSTR + kc * 8 + 2 * tq];
                mma_bf16(acc, oa[kc], bb.x, bb.y);
            }
            int c0 = cbase + nt * 8 + 2 * tq;
            int q0 = i0 + qb + gq;
            float bb0 = out_b[c0], bb1 = out_b[c0 + 1];
            size_t o00 = ((size_t)n * Cc + c0    ) * Nn + q0;
            size_t o10 = ((size_t)n * Cc + c0 + 1) * Nn + q0;
            out[o00]     = gm * (acc[0] + bb0) + x[o00];
            out[o10]     = gm * (acc[1] + bb1) + x[o10];
            out[o00 + 8] = gm * (acc[2] + bb0) + x[o00 + 8];
            out[o10 + 8] = gm * (acc[3] + bb1) + x[o10 + 8];
        }
    }
}

// ---------------------------------------------------------------------------
extern "C" void kernel_launch(void* const* d_in, const int* in_sizes, int n_in,
                              void* d_out, int out_size)
{
    const float* x       = (const float*)d_in[0];
    const float* theta_w = (const float*)d_in[1];
    const float* theta_b = (const float*)d_in[2];
    const float* phi_w   = (const float*)d_in[3];
    const float* phi_b   = (const float*)d_in[4];
    const float* g_w     = (const float*)d_in[5];
    const float* g_b     = (const float*)d_in[6];
    const float* out_w   = (const float*)d_in[7];
    const float* out_b   = (const float*)d_in[8];
    const float* gamma   = (const float*)d_in[9];
    float* out = (float*)d_out;

    const int smem1 = 13312 * 4;   // 53 KB
    // phase1: phi 2*128*16*4 = 16384 B + G 2*128*80*4 = 81920 B -> 98304 B (96 KB)
    // phase3: W pane 256*72*4 = 73728 B (aliases)
    const int smem2 = 98304;

    cudaFuncSetAttribute(proj_mma_kernel,   cudaFuncAttributeMaxDynamicSharedMemorySize, smem1);
    cudaFuncSetAttribute(attn_fused_kernel, cudaFuncAttributeMaxDynamicSharedMemorySize, smem2);

    proj_mma_kernel<<<dim3(32, 3, Bn), 256, smem1>>>(x, theta_w, theta_b,
                                                     phi_w, phi_b, g_w, g_b);
    attn_fused_kernel<<<dim3(32, Bn), 256, smem2>>>(x, out_w, out_b, gamma, out);
}

// round 15
// speedup vs baseline: 1.5854x; 1.5854x over previous
#include <cuda_runtime.h>
#include <cuda_bf16.h>
#include <cstddef>
#include <cstdint>

#define Bn 8
#define Cc 256
#define Nn 4096      // 64*64 spatial
#define Mm 1024      // 32*32 pooled
#define Dd 32
#define Dv 128

// Scratch (device globals; no allocations allowed)
// g_theta: (n, i, d) fp32 plain
// g_phib:  (n, j, d) bf16, d reordered per row for uint4 fragment gather
// g_gp:    (n, v, j) bf16, j reordered per 32-j slice for uint4 gather
__device__ float          g_theta[Bn * Nn * Dd];
__device__ __nv_bfloat16  g_phib [Bn * Mm * Dd];
__device__ __nv_bfloat16  g_gp   [Bn * Dv * Mm];

__device__ __forceinline__ void mma_tf32(float c[4], const uint32_t a[4],
                                         uint32_t b0, uint32_t b1) {
    asm volatile("mma.sync.aligned.m16n8k8.row.col.f32.tf32.tf32.f32 "
        "{%0,%1,%2,%3}, {%4,%5,%6,%7}, {%8,%9}, {%0,%1,%2,%3};"
        : "+f"(c[0]), "+f"(c[1]), "+f"(c[2]), "+f"(c[3])
        : "r"(a[0]), "r"(a[1]), "r"(a[2]), "r"(a[3]), "r"(b0), "r"(b1));
}
__device__ __forceinline__ void mma_bf16(float c[4], const uint32_t a[4],
                                         uint32_t b0, uint32_t b1) {
    asm volatile("mma.sync.aligned.m16n8k16.row.col.f32.bf16.bf16.f32 "
        "{%0,%1,%2,%3}, {%4,%5,%6,%7}, {%8,%9}, {%0,%1,%2,%3};"
        : "+f"(c[0]), "+f"(c[1]), "+f"(c[2]), "+f"(c[3])
        : "r"(a[0]), "r"(a[1]), "r"(a[2]), "r"(a[3]), "r"(b0), "r"(b1));
}
__device__ __forceinline__ uint32_t pkbf(float lo, float hi) {
    uint32_t r;
    asm("cvt.rn.bf16x2.f32 %0, %1, %2;" : "=r"(r) : "f"(hi), "f"(lo));
    return r;
}
__device__ __forceinline__ void cp16(void* dst_smem, const void* src) {
    uint32_t d = (uint32_t)__cvta_generic_to_shared(dst_smem);
    asm volatile("cp.async.cg.shared.global [%0], [%1], 16;\n" :: "r"(d), "l"(src));
}
__device__ __forceinline__ void cp_commit() {
    asm volatile("cp.async.commit_group;\n");
}
template<int N> __device__ __forceinline__ void cp_wait() {
    asm volatile("cp.async.wait_group %0;\n" :: "n"(N));
}
// position of element r within its 8-group under [0,4,1,5,2,6,3,7] order
__device__ __forceinline__ int perm8(int r) {
    return (r < 4) ? 2 * r : 2 * (r - 4) + 1;
}

// ---------------------------------------------------------------------------
// Kernel 1: fused projections + maxpool, tf32 MMA, single-barrier pipeline.
// phi/g written bf16 with uint4-fragment reordering (see kernel 2 layout).
// ---------------------------------------------------------------------------
#define WS  36
#define XSS 136
#define YSS 132

__global__ void __launch_bounds__(256, 3) proj_mma_kernel(
    const float* __restrict__ x,
    const float* __restrict__ theta_w, const float* __restrict__ theta_b,
    const float* __restrict__ phi_w,   const float* __restrict__ phi_b,
    const float* __restrict__ g_w,     const float* __restrict__ g_b)
{
    extern __shared__ float sm[];
    float* Ws = sm;                    // 2 x 64 x 36
    float* Xs = sm + 2 * 64 * WS;      // 2 x 32 x 136
    float* Ys = sm;                    // 64 x 132 (aliases pipeline)

    const int bi  = blockIdx.x;
    const int grp = blockIdx.y;
    const int n   = blockIdx.z;
    const int t   = threadIdx.x;
    const int w   = t >> 5, lane = t & 31;
    const int gq  = lane >> 2, tq = lane & 3;
    const int mrow = (w & 3) * 16;
    const int nc0  = (w >> 2) * 64;
    const int base = bi * 128;

    const float* xb = x + (size_t)n * Cc * Nn;

    auto issue = [&](int c8) {
        int kc = c8 * 32;
        float* Wb = Ws + (c8 & 1) * 64 * WS;
        float* Xb = Xs + (c8 & 1) * 32 * XSS;
#pragma unroll
        for (int it = 0; it < 2; it++) {
            int idx = t + it * 256;
            int r = idx >> 3, kq = (idx & 7) * 4;
            const float* src;
            if (grp == 0) src = (r < 32) ? &theta_w[r * Cc + kc + kq]
                                         : &phi_w[(r - 32) * Cc + kc + kq];
            else          src = &g_w[((grp - 1) * 64 + r) * Cc + kc + kq];
            cp16(&Wb[r * WS + kq], src);
        }
#pragma unroll
        for (int it = 0; it < 4; it++) {
            int idx = t + it * 256;
            int k = idx >> 5, i4 = (idx & 31) * 4;
            cp16(&Xb[k * XSS + i4], &xb[(size_t)(kc + k) * Nn + base + i4]);
        }
        cp_commit();
    };

    float acc[8][4];
#pragma unroll
    for (int nt = 0; nt < 8; nt++)
#pragma unroll
        for (int c = 0; c < 4; c++) acc[nt][c] = 0.f;

    issue(0);
    for (int c8 = 0; c8 < 8; c8++) {
        cp_wait<0>();
        __syncthreads();
        if (c8 + 1 < 8) issue(c8 + 1);

        const float* Wb = Ws + (c8 & 1) * 64 * WS;
        const float* Xb = Xs + (c8 & 1) * 32 * XSS;
#pragma unroll
        for (int ks = 0; ks < 4; ks++) {
            uint32_t a[4];
            a[0] = __float_as_uint(Wb[(mrow + gq    ) * WS + ks * 8 + tq    ]);
            a[1] = __float_as_uint(Wb[(mrow + gq + 8) * WS + ks * 8 + tq    ]);
            a[2] = __float_as_uint(Wb[(mrow + gq    ) * WS + ks * 8 + tq + 4]);
            a[3] = __float_as_uint(Wb[(mrow + gq + 8) * WS + ks * 8 + tq + 4]);
#pragma unroll
            for (int nt = 0; nt < 8; nt++) {
                uint32_t b0 = __float_as_uint(Xb[(ks * 8 + tq    ) * XSS + nc0 + nt * 8 + gq]);
                uint32_t b1 = __float_as_uint(Xb[(ks * 8 + tq + 4) * XSS + nc0 + nt * 8 + gq]);
                mma_tf32(acc[nt], a, b0, b1);
            }
        }
    }
    __syncthreads();   // all fragment reads done before Ys aliases pipeline

    {
        int r0 = mrow + gq, r1 = mrow + gq + 8;
        float b0, b1;
        if (grp == 0) {
            b0 = (r0 < 32) ? theta_b[r0] : phi_b[r0 - 32];
            b1 = (r1 < 32) ? theta_b[r1] : phi_b[r1 - 32];
        } else {
            b0 = g_b[(grp - 1) * 64 + r0];
            b1 = g_b[(grp - 1) * 64 + r1];
        }
#pragma unroll
        for (int nt = 0; nt < 8; nt++) {
            int col = nc0 + nt * 8 + tq * 2;
            *(float2*)&Ys[r0 * YSS + col] = make_float2(acc[nt][0] + b0, acc[nt][1] + b0);
            *(float2*)&Ys[r1 * YSS + col] = make_float2(acc[nt][2] + b1, acc[nt][3] + b1);
        }
    }
    __syncthreads();

    if (grp == 0) {
        // theta rows 0..31 -> (n, i, d) fp32
        for (int idx = t; idx < 32 * 128; idx += 256) {
            int o = idx & 31, i = idx >> 5;
            g_theta[((size_t)n * Nn + base + i) * Dd + o] = Ys[o * YSS + i];
        }
        // phi rows 32..63 -> maxpool -> (n, j, d_reordered) bf16
        // row (16 words): word (tq'*4 + kc*2 + sub); orig word w: tq'=w&3, sub=w>>2
        for (int idx = t; idx < 32 * 32; idx += 256) {
            int o = idx & 31, jw = idx >> 5;
            const float* yr = &Ys[(32 + o) * YSS];
            float m0 = fmaxf(yr[2 * jw],      yr[2 * jw + 1]);
            float m1 = fmaxf(yr[64 + 2 * jw], yr[64 + 2 * jw + 1]);
            int kc = o >> 4, wloc = (o & 15) >> 1, lo = o & 1;
            int pos = (((wloc & 3) * 4) + kc * 2 + (wloc >> 2)) * 2 + lo;
            g_phib[((size_t)n * Mm + bi * 32 + jw) * Dd + pos] =
                __float2bfloat16(fmaxf(m0, m1));
        }
    } else {
        int vbase = (grp - 1) * 64;
        // g -> maxpool -> (n, v, j_reordered) bf16 (32-j slice, same word map)
        for (int idx = t; idx < 64 * 32; idx += 256) {
            int jw = idx & 31, v = idx >> 5;
            const float* yr = &Ys[v * YSS];
            float m0 = fmaxf(yr[2 * jw],      yr[2 * jw + 1]);
            float m1 = fmaxf(yr[64 + 2 * jw], yr[64 + 2 * jw + 1]);
            int wl = jw >> 1, lo = jw & 1;
            int grp16 = wl >> 3, wloc = wl & 7;
            int pos = (((wloc & 3) * 4) + grp16 * 2 + (wloc >> 2)) * 2 + lo;
            g_gp[((size_t)n * Dv + vbase + v) * Mm + bi * 32 + pos] =
                __float2bfloat16(fmaxf(m0, m1));
        }
    }
}

// ---------------------------------------------------------------------------
// Kernel 2: FUSED flash attention + out conv + residual. ALL-bf16 MMA.
// LDS.128 fragment gathers, but liveness-bounded: pack pe before computing
// the second half's e-values; only pe/po (8 regs) live through the PV sweep.
// grid (32 q-tiles, 8 batches), 256 threads = 8 warps x 16 q.
// ---------------------------------------------------------------------------
#define KB    128
#define PHW   16   // phi row stride in words
#define GSW   80   // g row stride in words (64 data + 16 pad, ≡16 mod 32)
#define WSTR  72   // W pane row stride in words (phase 3)
#define NSTG  2

__global__ void __launch_bounds__(256, 2) attn_fused_kernel(
    const float* __restrict__ x,
    const float* __restrict__ out_w,
    const float* __restrict__ out_b,
    const float* __restrict__ gamma,
    float* __restrict__ out)
{
    extern __shared__ float sm[];
    uint32_t* Phw = (uint32_t*)sm;                         // 2 x 128 x 16 words
    uint32_t* Gsw = (uint32_t*)sm + NSTG * KB * PHW;       // 2 x 128 x 80 words
    uint32_t* Wsw = (uint32_t*)sm;                         // phase3: 256 x 72 words

    const int n  = blockIdx.y;
    const int i0 = blockIdx.x * 128;
    const int t  = threadIdx.x;
    const int w  = t >> 5;
    const int lane = t & 31;
    const int qb = w * 16;
    const int gq = lane >> 2;
    const int tq = lane & 3;

    // Q A-fragments, bf16 k16 x 2 chunks (persist)
    uint32_t qa[2][4];
    {
        const float* th = g_theta + ((size_t)n * Nn + i0 + qb) * Dd;
#pragma unroll
        for (int kc = 0; kc < 2; kc++) {
            qa[kc][0] = pkbf(th[(gq    ) * Dd + kc * 16 + 2 * tq],
                             th[(gq    ) * Dd + kc * 16 + 2 * tq + 1]);
            qa[kc][1] = pkbf(th[(gq + 8) * Dd + kc * 16 + 2 * tq],
                             th[(gq + 8) * Dd + kc * 16 + 2 * tq + 1]);
            qa[kc][2] = pkbf(th[(gq    ) * Dd + kc * 16 + 8 + 2 * tq],
                             th[(gq    ) * Dd + kc * 16 + 8 + 2 * tq + 1]);
            qa[kc][3] = pkbf(th[(gq + 8) * Dd + kc * 16 + 8 + 2 * tq],
                             th[(gq + 8) * Dd + kc * 16 + 8 + 2 * tq + 1]);
        }
    }

    auto issue = [&](int chunk) {
        int buf = chunk & 1;
        int jb = chunk * KB;
        uint32_t* Pb = Phw + buf * KB * PHW;
        uint32_t* Gb = Gsw + buf * Dv * GSW;
#pragma unroll
        for (int it = 0; it < 2; it++) {
            int idx = t + it * 256;                 // phi: 128 j x 4 cp16 -> 512
            int j = idx >> 2, c = idx & 3;
            cp16((__nv_bfloat16*)&Pb[j * PHW] + c * 8,
                 &g_phib[((size_t)n * Mm + jb + j) * Dd + c * 8]);
        }
#pragma unroll
        for (int it = 0; it < 8; it++) {
            int idx = t + it * 256;                 // g: 128 v x 16 cp16 -> 2048
            int vv = idx >> 4, p8 = (idx & 15) * 8;
            cp16((__nv_bfloat16*)&Gb[vv * GSW] + p8,
                 &g_gp[((size_t)n * Dv + vv) * Mm + jb + p8]);
        }
        cp_commit();
    };

    float oacc[16][4];
#pragma unroll
    for (int vt = 0; vt < 16; vt++)
#pragma unroll
        for (int c = 0; c < 4; c++) oacc[vt][c] = 0.f;

    float s0 = 0.f, s1 = 0.f;

    issue(0);
    for (int kb = 0; kb < Mm / KB; kb++) {
        cp_wait<0>();
        __syncthreads();
        if (kb + 1 < Mm / KB) issue(kb + 1);

        const uint32_t* Pw = Phw + (kb & 1) * KB * PHW;
        const uint32_t* Gb = Gsw + (kb & 1) * Dv * GSW;

        // per P (32 keys): two sequential energy halves -> pe, po; then PV.
#pragma unroll
        for (int P = 0; P < 4; P++) {
            uint32_t pe[4], po[4];
            // ---- half 0 (keys of p = 2P) ----
            {
                float ea[4] = {0.f, 0.f, 0.f, 0.f};
                float eb[4] = {0.f, 0.f, 0.f, 0.f};
                uint4 r0 = *(const uint4*)&Pw[((4*P    ) * 8 + gq) * PHW + tq * 4];
                uint4 r1 = *(const uint4*)&Pw[((4*P + 1) * 8 + gq) * PHW + tq * 4];
                mma_bf16(ea, qa[0], r0.x, r0.y);
                mma_bf16(eb, qa[0], r1.x, r1.y);
                mma_bf16(ea, qa[1], r0.z, r0.w);
                mma_bf16(eb, qa[1], r1.z, r1.w);
                ea[0] = __expf(ea[0]); ea[1] = __expf(ea[1]);
                ea[2] = __expf(ea[2]); ea[3] = __expf(ea[3]);
                eb[0] = __expf(eb[0]); eb[1] = __expf(eb[1]);
                eb[2] = __expf(eb[2]); eb[3] = __expf(eb[3]);
                s0 += ea[0] + ea[1] + eb[0] + eb[1];
                s1 += ea[2] + ea[3] + eb[2] + eb[3];
                pe[0] = pkbf(ea[0], ea[1]);
                pe[1] = pkbf(ea[2], ea[3]);
                pe[2] = pkbf(eb[0], eb[1]);
                pe[3] = pkbf(eb[2], eb[3]);
            }
            // ---- half 1 (keys of p = 2P+1) ----
            {
                float ec[4] = {0.f, 0.f, 0.f, 0.f};
                float ed[4] = {0.f, 0.f, 0.f, 0.f};
                uint4 r2 = *(const uint4*)&Pw[((4*P + 2) * 8 + gq) * PHW + tq * 4];
                uint4 r3 = *(const uint4*)&Pw[((4*P + 3) * 8 + gq) * PHW + tq * 4];
                mma_bf16(ec, qa[0], r2.x, r2.y);
                mma_bf16(ed, qa[0], r3.x, r3.y);
                mma_bf16(ec, qa[1], r2.z, r2.w);
                mma_bf16(ed, qa[1], r3.z, r3.w);
                ec[0] = __expf(ec[0]); ec[1] = __expf(ec[1]);
                ec[2] = __expf(ec[2]); ec[3] = __expf(ec[3]);
                ed[0] = __expf(ed[0]); ed[1] = __expf(ed[1]);
                ed[2] = __expf(ed[2]); ed[3] = __expf(ed[3]);
                s0 += ec[0] + ec[1] + ed[0] + ed[1];
                s1 += ec[2] + ec[3] + ed[2] + ed[3];
                po[0] = pkbf(ec[0], ec[1]);
                po[1] = pkbf(ec[2], ec[3]);
                po[2] = pkbf(ed[0], ed[1]);
                po[3] = pkbf(ed[2], ed[3]);
            }
            // ---- PV: one uint4 per vt feeds both halves' MMAs ----
#pragma unroll
            for (int vt = 0; vt < 16; vt++) {
                uint4 g4 = *(const uint4*)&Gb[(vt * 8 + gq) * GSW + P * 16 + tq * 4];
                mma_bf16(oacc[vt], pe, g4.x, g4.y);
                mma_bf16(oacc[vt], po, g4.z, g4.w);
            }
        }
    }

    // ---- exp-sum reduce (once) and O pack ----
    s0 += __shfl_xor_sync(0xffffffff, s0, 1);
    s0 += __shfl_xor_sync(0xffffffff, s0, 2);
    s1 += __shfl_xor_sync(0xffffffff, s1, 1);
    s1 += __shfl_xor_sync(0xffffffff, s1, 2);

    uint32_t oa[8][4];
    {
        const float inv0 = 1.f / s0;
        const float inv1 = 1.f / s1;
#pragma unroll
        for (int kc = 0; kc < 8; kc++) {
            oa[kc][0] = pkbf(oacc[2*kc  ][0] * inv0, oacc[2*kc  ][1] * inv0);
            oa[kc][1] = pkbf(oacc[2*kc  ][2] * inv1, oacc[2*kc  ][3] * inv1);
            oa[kc][2] = pkbf(oacc[2*kc+1][0] * inv0, oacc[2*kc+1][1] * inv0);
            oa[kc][3] = pkbf(oacc[2*kc+1][2] * inv1, oacc[2*kc+1][3] * inv1);
        }
    }
    __syncthreads();   // all warps done with pipeline smem before W pane aliasing

    // ---- phase 3: out conv (bf16). Full W pane [256 c x 64 words] loaded once.
    const float gm = gamma[0];

#pragma unroll
    for (int it = 0; it < 32; it++) {
        int idx = t + it * 256;                  // 8192: 256 c x 32 float4
        int r = idx >> 5, v4 = (idx & 31) * 4;
        float4 wv = *(const float4*)&out_w[(size_t)r * Dv + v4];
        uint32_t w0 = pkbf(wv.x, wv.y);
        uint32_t w1 = pkbf(wv.z, wv.w);
        int wi0 = v4 >> 1, wi1 = wi0 + 1;
        Wsw[r * WSTR + (wi0 & ~7) + perm8(wi0 & 7)] = w0;
        Wsw[r * WSTR + (wi1 & ~7) + perm8(wi1 & 7)] = w1;
    }
    __syncthreads();

#pragma unroll
    for (int pass = 0; pass < 4; pass++) {
        const int cbase = pass * 64;
#pragma unroll
        for (int nt = 0; nt < 8; nt++) {
            float acc[4] = {0.f, 0.f, 0.f, 0.f};
#pragma unroll
            for (int kc = 0; kc < 8; kc++) {
                uint2 bb = *(const uint2*)&Wsw[(cbase + nt * 8 + gq) * WSTR + kc * 8 + 2 * tq];
                mma_bf16(acc, oa[kc], bb.x, bb.y);
            }
            int c0 = cbase + nt * 8 + 2 * tq;
            int q0 = i0 + qb + gq;
            float bb0 = out_b[c0], bb1 = out_b[c0 + 1];
            size_t o00 = ((size_t)n * Cc + c0    ) * Nn + q0;
            size_t o10 = ((size_t)n * Cc + c0 + 1) * Nn + q0;
            out[o00]     = gm * (acc[0] + bb0) + x[o00];
            out[o10]     = gm * (acc[1] + bb1) + x[o10];
            out[o00 + 8] = gm * (acc[2] + bb0) + x[o00 + 8];
            out[o10 + 8] = gm * (acc[3] + bb1) + x[o10 + 8];
        }
    }
}

// ---------------------------------------------------------------------------
extern "C" void kernel_launch(void* const* d_in, const int* in_sizes, int n_in,
                              void* d_out, int out_size)
{
    const float* x       = (const float*)d_in[0];
    const float* theta_w = (const float*)d_in[1];
    const float* theta_b = (const float*)d_in[2];
    const float* phi_w   = (const float*)d_in[3];
    const float* phi_b   = (const float*)d_in[4];
    const float* g_w     = (const float*)d_in[5];
    const float* g_b     = (const float*)d_in[6];
    const float* out_w   = (const float*)d_in[7];
    const float* out_b   = (const float*)d_in[8];
    const float* gamma   = (const float*)d_in[9];
    float* out = (float*)d_out;

    const int smem1 = 13312 * 4;   // 53 KB
    // phase1: phi 2*128*16*4 = 16384 B + G 2*128*80*4 = 81920 B -> 98304 B (96 KB)
    // phase3: W pane 256*72*4 = 73728 B (aliases)
    const int smem2 = 98304;

    cudaFuncSetAttribute(proj_mma_kernel,   cudaFuncAttributeMaxDynamicSharedMemorySize, smem1);
    cudaFuncSetAttribute(attn_fused_kernel, cudaFuncAttributeMaxDynamicSharedMemorySize, smem2);

    proj_mma_kernel<<<dim3(32, 3, Bn), 256, smem1>>>(x, theta_w, theta_b,
                                                     phi_w, phi_b, g_w, g_b);
    attn_fused_kernel<<<dim3(32, Bn), 256, smem2>>>(x, out_w, out_b, gamma, out);
}